// round 1
// baseline (speedup 1.0000x reference)
#include <cuda_runtime.h>
#include <cuda_bf16.h>
#include <math.h>

#define MAXN 65536
#define LN_EPS 1e-5f
#define CLAMP_MIN 1e-5f

// Scratch (device globals — no allocation allowed)
__device__ unsigned char g_pred[MAXN];
__device__ float g_f1[MAXN];
__device__ float g_f2[MAXN];
__device__ float g_stats[4];  // mean1, inv_std1, mean2, inv_std2

// ---------------------------------------------------------------------------
// Kernel 1: per-node argmax of logits -> pred (uint8). First-max semantics.
// ---------------------------------------------------------------------------
__global__ void k_pred(const float* __restrict__ logits, int n, int C) {
    int i = blockIdx.x * blockDim.x + threadIdx.x;
    if (i >= n) return;
    const float* row = logits + (size_t)i * C;
    float best = row[0];
    int bi = 0;
    for (int c = 1; c < C; c++) {
        float v = __ldg(&row[c]);
        if (v > best) { best = v; bi = c; }   // strict > keeps first max (jnp.argmax)
    }
    g_pred[i] = (unsigned char)bi;
}

// ---------------------------------------------------------------------------
// Kernel 2: per-node neighbor-pred histogram -> f1 (agreement count) and
// f2 (negative sum k*log(clip(k,1e-5))). 16 classes packed as 8-bit counters
// in 4 uint32 registers (max count D=32 fits in 8 bits).
// ---------------------------------------------------------------------------
__global__ void k_feat(const int* __restrict__ nbr, int n, int D, int C) {
    int i = blockIdx.x * blockDim.x + threadIdx.x;
    if (i >= n) return;
    unsigned int cnt[4] = {0u, 0u, 0u, 0u};
    const int* row = nbr + (size_t)i * D;
    for (int d = 0; d < D; d++) {
        int j = __ldg(&row[d]);
        int p = (int)g_pred[j];
        cnt[p >> 2] += 1u << ((p & 3) * 8);
    }
    int cp = (int)g_pred[i];
    float f1 = (float)((cnt[cp >> 2] >> ((cp & 3) * 8)) & 0xffu);
    float f2 = 0.f;
    #pragma unroll
    for (int w = 0; w < 4; w++) {
        unsigned int v = cnt[w];
        #pragma unroll
        for (int b = 0; b < 4; b++) {
            int cls = w * 4 + b;
            if (cls < C) {
                float k = (float)((v >> (b * 8)) & 0xffu);
                float p = fmaxf(k, CLAMP_MIN);
                f2 -= p * __logf(p);
            }
        }
    }
    g_f1[i] = f1;
    g_f2[i] = f2;
}

// ---------------------------------------------------------------------------
// Kernel 3: single-block deterministic reduction -> mean / inv_std of f1, f2.
// Double accumulators (tiny op count; avoids E[x^2]-mean^2 cancellation risk).
// ---------------------------------------------------------------------------
__global__ void k_stats(int n) {
    double s1 = 0, q1 = 0, s2 = 0, q2 = 0;
    for (int i = threadIdx.x; i < n; i += blockDim.x) {
        double a = (double)g_f1[i];
        double b = (double)g_f2[i];
        s1 += a; q1 += a * a;
        s2 += b; q2 += b * b;
    }
    __shared__ double sh[4][32];
    int lane = threadIdx.x & 31, wid = threadIdx.x >> 5;
    for (int o = 16; o; o >>= 1) {
        s1 += __shfl_down_sync(0xffffffffu, s1, o);
        q1 += __shfl_down_sync(0xffffffffu, q1, o);
        s2 += __shfl_down_sync(0xffffffffu, s2, o);
        q2 += __shfl_down_sync(0xffffffffu, q2, o);
    }
    if (lane == 0) { sh[0][wid] = s1; sh[1][wid] = q1; sh[2][wid] = s2; sh[3][wid] = q2; }
    __syncthreads();
    if (wid == 0) {
        int nw = blockDim.x >> 5;
        s1 = (lane < nw) ? sh[0][lane] : 0.0;
        q1 = (lane < nw) ? sh[1][lane] : 0.0;
        s2 = (lane < nw) ? sh[2][lane] : 0.0;
        q2 = (lane < nw) ? sh[3][lane] : 0.0;
        for (int o = 16; o; o >>= 1) {
            s1 += __shfl_down_sync(0xffffffffu, s1, o);
            q1 += __shfl_down_sync(0xffffffffu, q1, o);
            s2 += __shfl_down_sync(0xffffffffu, s2, o);
            q2 += __shfl_down_sync(0xffffffffu, q2, o);
        }
        if (lane == 0) {
            double inv_n = 1.0 / (double)n;
            double m1 = s1 * inv_n, m2 = s2 * inv_n;
            double v1 = q1 * inv_n - m1 * m1;
            double v2 = q2 * inv_n - m2 * m2;
            g_stats[0] = (float)m1;
            g_stats[1] = (float)(1.0 / sqrt(v1 + (double)LN_EPS));
            g_stats[2] = (float)m2;
            g_stats[3] = (float)(1.0 / sqrt(v2 + (double)LN_EPS));
        }
    }
}

// ---------------------------------------------------------------------------
// Kernel 4: fused gather + epilogue. One warp per node; lane = float4 column.
// D==32 specialization: fully unrolled neighbor loop -> 32 in-flight LDG.128
// per thread (deep MLP, L2-latency hidden).
// ---------------------------------------------------------------------------
__global__ void __launch_bounds__(256)
k_main32(const float* __restrict__ h, const float* __restrict__ old_z,
         const float* __restrict__ tau1, const float* __restrict__ tau2,
         const int* __restrict__ nbr,
         float* __restrict__ out_h, float* __restrict__ out_z,
         int n, int F4) {
    int w = (int)((blockIdx.x * blockDim.x + threadIdx.x) >> 5);
    int lane = threadIdx.x & 31;
    if (w >= n) return;

    int j = __ldg(&nbr[(size_t)w * 32 + lane]);

    // z / gate (all lanes compute; broadcast loads hit L1/L2 same address)
    float nf1 = (g_f1[w] - g_stats[0]) * g_stats[1];
    float nf2 = (g_f2[w] - g_stats[2]) * g_stats[3];
    float t1 = __ldg(tau1), t2 = __ldg(tau2);
    float z = __frcp_rn(1.f + __expf(nf1 - t1)) * __frcp_rn(1.f + __expf(nf2 - t2));
    float gate = fminf(__ldg(&old_z[w]), z);

    const float4* hp = (const float4*)h;
    for (int col = lane; col < F4; col += 32) {
        float a0 = 0.f, a1 = 0.f, a2 = 0.f, a3 = 0.f;
        #pragma unroll
        for (int d = 0; d < 32; d++) {
            int idx = __shfl_sync(0xffffffffu, j, d);
            float4 v = __ldg(&hp[(size_t)idx * F4 + col]);
            a0 += v.x; a1 += v.y; a2 += v.z; a3 += v.w;
        }
        float4 hc = __ldg(&hp[(size_t)w * F4 + col]);
        float4 o;
        o.x = hc.x + gate * fmaxf(a0, 0.f);
        o.y = hc.y + gate * fmaxf(a1, 0.f);
        o.z = hc.z + gate * fmaxf(a2, 0.f);
        o.w = hc.w + gate * fmaxf(a3, 0.f);
        ((float4*)out_h)[(size_t)w * F4 + col] = o;
    }
    if (lane == 0) out_z[w] = z;
}

// Generic fallback (any D), correctness safety net.
__global__ void __launch_bounds__(256)
k_main_gen(const float* __restrict__ h, const float* __restrict__ old_z,
           const float* __restrict__ tau1, const float* __restrict__ tau2,
           const int* __restrict__ nbr,
           float* __restrict__ out_h, float* __restrict__ out_z,
           int n, int F4, int D) {
    int w = (int)((blockIdx.x * blockDim.x + threadIdx.x) >> 5);
    int lane = threadIdx.x & 31;
    if (w >= n) return;

    float nf1 = (g_f1[w] - g_stats[0]) * g_stats[1];
    float nf2 = (g_f2[w] - g_stats[2]) * g_stats[3];
    float t1 = __ldg(tau1), t2 = __ldg(tau2);
    float z = __frcp_rn(1.f + __expf(nf1 - t1)) * __frcp_rn(1.f + __expf(nf2 - t2));
    float gate = fminf(__ldg(&old_z[w]), z);

    const float4* hp = (const float4*)h;
    for (int col = lane; col < F4; col += 32) {
        float a0 = 0.f, a1 = 0.f, a2 = 0.f, a3 = 0.f;
        for (int d = 0; d < D; d++) {
            int idx = __ldg(&nbr[(size_t)w * D + d]);
            float4 v = __ldg(&hp[(size_t)idx * F4 + col]);
            a0 += v.x; a1 += v.y; a2 += v.z; a3 += v.w;
        }
        float4 hc = __ldg(&hp[(size_t)w * F4 + col]);
        float4 o;
        o.x = hc.x + gate * fmaxf(a0, 0.f);
        o.y = hc.y + gate * fmaxf(a1, 0.f);
        o.z = hc.z + gate * fmaxf(a2, 0.f);
        o.w = hc.w + gate * fmaxf(a3, 0.f);
        ((float4*)out_h)[(size_t)w * F4 + col] = o;
    }
    if (lane == 0) out_z[w] = z;
}

extern "C" void kernel_launch(void* const* d_in, const int* in_sizes, int n_in,
                              void* d_out, int out_size) {
    const float* h      = (const float*)d_in[0];
    const float* logits = (const float*)d_in[1];
    const float* old_z  = (const float*)d_in[2];
    const float* tau1   = (const float*)d_in[3];
    const float* tau2   = (const float*)d_in[4];
    const int*   nbr    = (const int*)d_in[5];

    int n = in_sizes[2];                 // old_z length = N
    int F = in_sizes[0] / n;             // 128
    int C = in_sizes[1] / n;             // 16
    int D = in_sizes[5] / n;             // 32
    int F4 = F / 4;

    float* out_h = (float*)d_out;
    float* out_z = out_h + (size_t)n * F;

    int tb = 256;
    k_pred<<<(n + tb - 1) / tb, tb>>>(logits, n, C);
    k_feat<<<(n + tb - 1) / tb, tb>>>(nbr, n, D, C);
    k_stats<<<1, 1024>>>(n);

    int warps_per_block = tb / 32;
    int blocks = (n + warps_per_block - 1) / warps_per_block;
    if (D == 32) {
        k_main32<<<blocks, tb>>>(h, old_z, tau1, tau2, nbr, out_h, out_z, n, F4);
    } else {
        k_main_gen<<<blocks, tb>>>(h, old_z, tau1, tau2, nbr, out_h, out_z, n, F4, D);
    }
}

// round 2
// speedup vs baseline: 2.2185x; 2.2185x over previous
#include <cuda_runtime.h>
#include <cuda_bf16.h>
#include <math.h>

#define MAXN 65536
#define MAXB 1024
#define LN_EPS 1e-5f
#define CLAMP_MIN 1e-5f

// Scratch (device globals — no allocation allowed)
__device__ unsigned char g_pred[MAXN];
__device__ float g_f1[MAXN];
__device__ float g_f2[MAXN];
__device__ double g_part[4 * MAXB];   // per-block partial sums: s1,q1,s2,q2
__device__ float g_stats[4];          // mean1, inv_std1, mean2, inv_std2

__device__ __forceinline__ void addf32x2(unsigned long long& a, unsigned long long b) {
    asm("add.rn.f32x2 %0, %1, %2;" : "=l"(a) : "l"(a), "l"(b));
}

// ---------------------------------------------------------------------------
// Kernel 1: per-node argmax of logits -> pred (uint8). First-max semantics.
// ---------------------------------------------------------------------------
__global__ void k_pred(const float* __restrict__ logits, int n, int C) {
    int i = blockIdx.x * blockDim.x + threadIdx.x;
    if (i >= n) return;
    const float* row = logits + (size_t)i * C;
    float best = __ldg(&row[0]);
    int bi = 0;
    for (int c = 1; c < C; c++) {
        float v = __ldg(&row[c]);
        if (v > best) { best = v; bi = c; }   // strict > keeps first max (jnp.argmax)
    }
    g_pred[i] = (unsigned char)bi;
}

// ---------------------------------------------------------------------------
// Kernel 2: per-node neighbor-pred histogram -> f1, f2; PLUS fused per-block
// partial sums (double) for the global LayerNorm statistics.
// ---------------------------------------------------------------------------
__global__ void __launch_bounds__(256)
k_feat(const int* __restrict__ nbr, int n, int D, int C) {
    int i = blockIdx.x * blockDim.x + threadIdx.x;
    float f1 = 0.f, f2 = 0.f;
    if (i < n) {
        unsigned int cnt[4] = {0u, 0u, 0u, 0u};
        const int* row = nbr + (size_t)i * D;
        for (int d = 0; d < D; d++) {
            int j = __ldg(&row[d]);
            int p = (int)g_pred[j];
            cnt[p >> 2] += 1u << ((p & 3) * 8);
        }
        int cp = (int)g_pred[i];
        f1 = (float)((cnt[cp >> 2] >> ((cp & 3) * 8)) & 0xffu);
        #pragma unroll
        for (int w = 0; w < 4; w++) {
            unsigned int v = cnt[w];
            #pragma unroll
            for (int b = 0; b < 4; b++) {
                float k = (float)((v >> (b * 8)) & 0xffu);
                float p = fmaxf(k, CLAMP_MIN);
                f2 -= p * __logf(p);
            }
        }
        g_f1[i] = f1;
        g_f2[i] = f2;
    }
    // --- fused block reduction (deterministic) ---
    double s1 = (double)f1, q1 = (double)f1 * f1;
    double s2 = (double)f2, q2 = (double)f2 * f2;
    __shared__ double sh[4][8];
    int lane = threadIdx.x & 31, wid = threadIdx.x >> 5;
    for (int o = 16; o; o >>= 1) {
        s1 += __shfl_down_sync(0xffffffffu, s1, o);
        q1 += __shfl_down_sync(0xffffffffu, q1, o);
        s2 += __shfl_down_sync(0xffffffffu, s2, o);
        q2 += __shfl_down_sync(0xffffffffu, q2, o);
    }
    if (lane == 0) { sh[0][wid] = s1; sh[1][wid] = q1; sh[2][wid] = s2; sh[3][wid] = q2; }
    __syncthreads();
    if (threadIdx.x == 0) {
        s1 = 0; q1 = 0; s2 = 0; q2 = 0;
        #pragma unroll
        for (int k = 0; k < 8; k++) { s1 += sh[0][k]; q1 += sh[1][k]; s2 += sh[2][k]; q2 += sh[3][k]; }
        g_part[0 * MAXB + blockIdx.x] = s1;
        g_part[1 * MAXB + blockIdx.x] = q1;
        g_part[2 * MAXB + blockIdx.x] = s2;
        g_part[3 * MAXB + blockIdx.x] = q2;
    }
}

// ---------------------------------------------------------------------------
// Kernel 3: tiny reduction over per-block partials -> mean / inv_std.
// ---------------------------------------------------------------------------
__global__ void k_stats(int n, int nb) {
    double s1 = 0, q1 = 0, s2 = 0, q2 = 0;
    for (int b = threadIdx.x; b < nb; b += blockDim.x) {
        s1 += g_part[0 * MAXB + b];
        q1 += g_part[1 * MAXB + b];
        s2 += g_part[2 * MAXB + b];
        q2 += g_part[3 * MAXB + b];
    }
    __shared__ double sh[4][32];
    int lane = threadIdx.x & 31, wid = threadIdx.x >> 5;
    for (int o = 16; o; o >>= 1) {
        s1 += __shfl_down_sync(0xffffffffu, s1, o);
        q1 += __shfl_down_sync(0xffffffffu, q1, o);
        s2 += __shfl_down_sync(0xffffffffu, s2, o);
        q2 += __shfl_down_sync(0xffffffffu, q2, o);
    }
    if (lane == 0) { sh[0][wid] = s1; sh[1][wid] = q1; sh[2][wid] = s2; sh[3][wid] = q2; }
    __syncthreads();
    if (threadIdx.x == 0) {
        int nw = blockDim.x >> 5;
        s1 = 0; q1 = 0; s2 = 0; q2 = 0;
        for (int k = 0; k < nw; k++) { s1 += sh[0][k]; q1 += sh[1][k]; s2 += sh[2][k]; q2 += sh[3][k]; }
        double inv_n = 1.0 / (double)n;
        double m1 = s1 * inv_n, m2 = s2 * inv_n;
        double v1 = q1 * inv_n - m1 * m1;
        double v2 = q2 * inv_n - m2 * m2;
        g_stats[0] = (float)m1;
        g_stats[1] = (float)(1.0 / sqrt(v1 + (double)LN_EPS));
        g_stats[2] = (float)m2;
        g_stats[3] = (float)(1.0 / sqrt(v2 + (double)LN_EPS));
    }
}

// ---------------------------------------------------------------------------
// Kernel 4 (D==32, F==128): one warp per node, lane = float4 column.
// Software-pipelined gather: double-buffered groups of 8 float4 loads
// (sustained MLP ~8-16/thread), packed f32x2 accumulation (2 chains).
// ---------------------------------------------------------------------------
__global__ void __launch_bounds__(128)
k_main32(const float* __restrict__ h, const float* __restrict__ old_z,
         const float* __restrict__ tau1, const float* __restrict__ tau2,
         const int* __restrict__ nbr,
         float* __restrict__ out_h, float* __restrict__ out_z, int n) {
    int w = (int)((blockIdx.x * blockDim.x + threadIdx.x) >> 5);
    int lane = threadIdx.x & 31;
    if (w >= n) return;

    int j = __ldg(&nbr[(size_t)w * 32 + lane]);

    const ulonglong2* hp = (const ulonglong2*)h;  // 16B granules; row stride = 32
    ulonglong2 buf[2][8];
    #pragma unroll
    for (int d = 0; d < 8; d++) {
        int idx = __shfl_sync(0xffffffffu, j, d);
        buf[0][d] = __ldg(&hp[(size_t)idx * 32 + lane]);
    }

    unsigned long long a0 = 0ull, a1 = 0ull, b0 = 0ull, b1 = 0ull;
    #pragma unroll
    for (int g = 0; g < 4; g++) {
        const int cur = g & 1;
        if (g < 3) {
            #pragma unroll
            for (int d = 0; d < 8; d++) {
                int idx = __shfl_sync(0xffffffffu, j, (g + 1) * 8 + d);
                buf[cur ^ 1][d] = __ldg(&hp[(size_t)idx * 32 + lane]);
            }
        }
        #pragma unroll
        for (int d = 0; d < 8; d += 2) {
            addf32x2(a0, buf[cur][d].x);
            addf32x2(a1, buf[cur][d].y);
            addf32x2(b0, buf[cur][d + 1].x);
            addf32x2(b1, buf[cur][d + 1].y);
        }
    }
    addf32x2(a0, b0);
    addf32x2(a1, b1);
    float2 lo = *(float2*)&a0;  // columns 4*lane + {0,1}
    float2 hi = *(float2*)&a1;  // columns 4*lane + {2,3}

    // z / gate
    float nf1 = (g_f1[w] - g_stats[0]) * g_stats[1];
    float nf2 = (g_f2[w] - g_stats[2]) * g_stats[3];
    float t1 = __ldg(tau1), t2 = __ldg(tau2);
    float z = __frcp_rn(1.f + __expf(nf1 - t1)) * __frcp_rn(1.f + __expf(nf2 - t2));
    float gate = fminf(__ldg(&old_z[w]), z);

    float4 hc = __ldg(&((const float4*)h)[(size_t)w * 32 + lane]);
    float4 o;
    o.x = hc.x + gate * fmaxf(lo.x, 0.f);
    o.y = hc.y + gate * fmaxf(lo.y, 0.f);
    o.z = hc.z + gate * fmaxf(hi.x, 0.f);
    o.w = hc.w + gate * fmaxf(hi.y, 0.f);
    ((float4*)out_h)[(size_t)w * 32 + lane] = o;
    if (lane == 0) out_z[w] = z;
}

// Generic fallback (any D / F multiple of 4), correctness safety net.
__global__ void __launch_bounds__(256)
k_main_gen(const float* __restrict__ h, const float* __restrict__ old_z,
           const float* __restrict__ tau1, const float* __restrict__ tau2,
           const int* __restrict__ nbr,
           float* __restrict__ out_h, float* __restrict__ out_z,
           int n, int F4, int D) {
    int w = (int)((blockIdx.x * blockDim.x + threadIdx.x) >> 5);
    int lane = threadIdx.x & 31;
    if (w >= n) return;

    float nf1 = (g_f1[w] - g_stats[0]) * g_stats[1];
    float nf2 = (g_f2[w] - g_stats[2]) * g_stats[3];
    float t1 = __ldg(tau1), t2 = __ldg(tau2);
    float z = __frcp_rn(1.f + __expf(nf1 - t1)) * __frcp_rn(1.f + __expf(nf2 - t2));
    float gate = fminf(__ldg(&old_z[w]), z);

    const float4* hp = (const float4*)h;
    for (int col = lane; col < F4; col += 32) {
        float a0 = 0.f, a1 = 0.f, a2 = 0.f, a3 = 0.f;
        for (int d = 0; d < D; d++) {
            int idx = __ldg(&nbr[(size_t)w * D + d]);
            float4 v = __ldg(&hp[(size_t)idx * F4 + col]);
            a0 += v.x; a1 += v.y; a2 += v.z; a3 += v.w;
        }
        float4 hc = __ldg(&hp[(size_t)w * F4 + col]);
        float4 o;
        o.x = hc.x + gate * fmaxf(a0, 0.f);
        o.y = hc.y + gate * fmaxf(a1, 0.f);
        o.z = hc.z + gate * fmaxf(a2, 0.f);
        o.w = hc.w + gate * fmaxf(a3, 0.f);
        ((float4*)out_h)[(size_t)w * F4 + col] = o;
    }
    if (lane == 0) out_z[w] = z;
}

extern "C" void kernel_launch(void* const* d_in, const int* in_sizes, int n_in,
                              void* d_out, int out_size) {
    const float* h      = (const float*)d_in[0];
    const float* logits = (const float*)d_in[1];
    const float* old_z  = (const float*)d_in[2];
    const float* tau1   = (const float*)d_in[3];
    const float* tau2   = (const float*)d_in[4];
    const int*   nbr    = (const int*)d_in[5];

    int n = in_sizes[2];                 // old_z length = N
    int F = in_sizes[0] / n;             // 128
    int C = in_sizes[1] / n;             // 16
    int D = in_sizes[5] / n;             // 32
    int F4 = F / 4;

    float* out_h = (float*)d_out;
    float* out_z = out_h + (size_t)n * F;

    int tb = 256;
    int nb = (n + tb - 1) / tb;
    k_pred<<<(n + tb - 1) / tb, tb>>>(logits, n, C);
    k_feat<<<nb, tb>>>(nbr, n, D, C);
    k_stats<<<1, 256>>>(n, nb);

    if (D == 32 && F == 128) {
        int blocks = (n + 3) / 4;        // 4 warps (nodes) per 128-thread block
        k_main32<<<blocks, 128>>>(h, old_z, tau1, tau2, nbr, out_h, out_z, n);
    } else {
        int warps_per_block = tb / 32;
        int blocks = (n + warps_per_block - 1) / warps_per_block;
        k_main_gen<<<blocks, tb>>>(h, old_z, tau1, tau2, nbr, out_h, out_z, n, F4, D);
    }
}